// round 14
// baseline (speedup 1.0000x reference)
#include <cuda_runtime.h>
#include <math.h>

namespace {
constexpr int B = 256, T = 64, S = 10, H = 128, IPT = 128, Q = 128;
constexpr int ROWLEN = 2 + IPT;
constexpr int HH = H * H;
constexpr long long HSEQ_ELEMS = (long long)B * T * S * H;
constexpr long long HC_ELEMS   = (long long)B * S * H;
// dynamic smem layout (float offsets)
constexpr int SM_W1  = 0;                   // [128][128]
constexpr int SM_W2  = SM_W1 + HH;
constexpr int SM_W3  = SM_W2 + HH;
constexpr int SM_HT  = SM_W3 + HH;          // [128][12]
constexpr int SM_BUF = SM_HT + H * 12;      // [128][12]
constexpr int SM_QPS = SM_BUF + H * 12;     // [2][10][128] double-buffered
constexpr int SM_SSM = SM_QPS + 2 * S * H;  // ssmT [64][12]
constexpr int SM_ATS = SM_SSM + T * 12;     // [10][128]
constexpr int SM_INV = SM_ATS + S * H;      // [16]
constexpr int SM_TOTAL = SM_INV + 16;       // 56848 floats = 227392 B
}

// ---------------- scratch ----------------
__device__ float g_qp[B * T * S * H];
__device__ float g_A [B * T * H * 6];
__device__ float g_pk[B * T * S * H];
__device__ float g_pv[B * T * S * H];
__device__ float g_Wc[H * H];
__device__ float g_bc[H];
__device__ float2 g_Wh01[H * H];
__device__ float2 g_Wh23[H * H];
__device__ float g_nvinv[T];
__device__ float g_lpart[B * T];
__device__ int   g_perm[B];

// ---------------- f32x2 helpers ----------------
using u64 = unsigned long long;
__device__ __forceinline__ u64 pk2(float lo, float hi) {
    u64 r; asm("mov.b64 %0,{%1,%2};" : "=l"(r) : "f"(lo), "f"(hi)); return r;
}
__device__ __forceinline__ u64 dup2(float x) { return pk2(x, x); }
__device__ __forceinline__ void un2(u64 v, float& a, float& b) {
    asm("mov.b64 {%0,%1},%2;" : "=f"(a), "=f"(b) : "l"(v));
}
__device__ __forceinline__ void fma2(u64& d, u64 a, u64 b) {
    asm("fma.rn.f32x2 %0,%1,%2,%0;" : "+l"(d) : "l"(a), "l"(b));
}

__device__ __forceinline__ float sigf(float x) {
    return __fdividef(1.f, 1.f + __expf(-x));
}
__device__ __forceinline__ float tanhfast(float x) {
    return __fdividef(2.f, 1.f + __expf(-2.f * x)) - 1.f;
}

// ---------------- fold: q-weights + Wh interleave + perm/nvinv ----------------
__global__ void __launch_bounds__(128) fold_kernel(
    const float* __restrict__ Wa, const float* __restrict__ ba,
    const float* __restrict__ Wattn, const float* __restrict__ battn,
    const float* __restrict__ Wh, const int* __restrict__ keys_length)
{
    const int bx = blockIdx.x, tid = threadIdx.x;
    if (bx < 128) {
        const int q = bx, h = tid;
        const float scale = 0.08838834764831845f;
        float acc = 0.f;
        for (int j = 0; j < H; ++j) acc += Wa[q * H + j] * Wattn[j * H + h];
        g_Wc[q * H + h] = acc * scale;
        if (q == 0) {
            float bacc = battn[h];
            for (int j = 0; j < H; ++j) bacc += ba[j] * Wattn[j * H + h];
            g_bc[h] = bacc * scale;
        }
        return;
    }
    const int e = (bx - 128) * 128 + tid;
    g_Wh01[e] = make_float2(Wh[e], Wh[HH + e]);
    g_Wh23[e] = make_float2(Wh[2 * HH + e], Wh[3 * HH + e]);

    if (bx == 128) {
#pragma unroll
        for (int half = 0; half < 2; ++half) {
            const int b = tid + half * 128;
            const int kb = keys_length[b];
            int rank = 0;
            for (int j = 0; j < B; ++j) {
                const int kj = keys_length[j];
                rank += (kj > kb) || (kj == kb && j < b);
            }
            g_perm[rank] = b;
        }
        if (tid < T) {
            int cnt = 0;
            for (int j = 0; j < B; ++j) cnt += (tid < keys_length[j]) ? 1 : 0;
            g_nvinv[tid] = cnt ? 1.f / (float)cnt : 0.f;
        }
    }
}

// ---------------- precompute A[B,T,H,6] (only t < kl) ----------------
__global__ void __launch_bounds__(128) pre_kernel(
    const float* __restrict__ inputs, const float* __restrict__ Wx,
    const float* __restrict__ Wts, const float* __restrict__ bg,
    const int* __restrict__ keys_length)
{
    const int b = blockIdx.x, k = threadIdx.x;
    const int kl = keys_length[b];
    if (kl == 0) return;
    __shared__ float xsT[IPT][66];
    __shared__ float Tts[T], Dts[T];
    const int tmax = kl;
    for (int idx = k; idx < tmax * IPT; idx += 128) {
        const int t = idx >> 7, i = idx & 127;
        xsT[i][t] = inputs[(long long)(b * T + t) * ROWLEN + 2 + i];
    }
    if (k < tmax) {
        Tts[k] = inputs[(long long)(b * T + k) * ROWLEN + 0];
        Dts[k] = inputs[(long long)(b * T + k) * ROWLEN + 1];
    }
    __syncthreads();

    const float wt0 = Wts[0 * H + k], wt1 = Wts[1 * H + k];
    const float wt2 = Wts[2 * H + k], wt3 = Wts[3 * H + k];
    const float wt4 = Wts[4 * H + k], wt5 = Wts[5 * H + k];
    float bgv[8];
#pragma unroll
    for (int g = 0; g < 8; ++g) bgv[g] = bg[g * H + k];

    for (int t0 = 0; t0 < tmax; t0 += 16) {
        const int nt = min(16, tmax - t0);
        float T1v[16], T2v[16];
#pragma unroll
        for (int g = 0; g < 8; ++g) {
            u64 acc[8];
#pragma unroll
            for (int j = 0; j < 8; ++j) acc[j] = 0ull;
            const float* Wg = Wx + (long long)g * IPT * H + k;
#pragma unroll 4
            for (int i = 0; i < IPT; ++i) {
                const u64 wd = dup2(Wg[(long long)i * H]);
#pragma unroll
                for (int j = 0; j < 8; ++j)
                    fma2(acc[j], *(const u64*)&xsT[i][t0 + 2 * j], wd);
            }
#pragma unroll
            for (int j = 0; j < 8; ++j) {
                float v0, v1; un2(acc[j], v0, v1);
#pragma unroll
                for (int half = 0; half < 2; ++half) {
                    const int tt = 2 * j + half;
                    if (tt >= nt) continue;
                    const int t = t0 + tt;
                    const float v = half ? v1 : v0;
                    float* At = g_A + (((long long)(b * T + t)) * H + k) * 6;
                    if (g == 0)      At[0] = v + bgv[0];
                    else if (g == 1) At[1] = v + bgv[1];
                    else if (g == 2) At[2] = v + bgv[2];
                    else if (g == 3) At[3] = v + Tts[t] * wt4 + Dts[t] * wt5 + bgv[3];
                    else if (g == 4) T1v[tt] = sigf(v + sigf(Tts[t] * wt0) + bgv[4]);
                    else if (g == 5) T2v[tt] = sigf(v + sigf(Tts[t] * wt1) + bgv[5]);
                    else if (g == 6) At[4] = T1v[tt] * sigf(v + sigf(Dts[t] * wt2) + bgv[6]);
                    else             At[5] = T2v[tt] * sigf(v + sigf(Dts[t] * wt3) + bgv[7]);
                }
            }
        }
    }
}

// ---------------- qp = x_q @ Wc + bc (only 1 <= t < kl) ----------------
__global__ void __launch_bounds__(128) qp_kernel(
    const float* __restrict__ x_q, const int* __restrict__ keys_length)
{
    const int bt = blockIdx.x, k = threadIdx.x;
    const int b = bt >> 6, t = bt & 63;
    if (t == 0 || t >= keys_length[b]) return;
    __shared__ float xqT[Q][12];
    const float* xp = x_q + (long long)bt * S * Q;
    for (int idx = k; idx < S * Q; idx += 128) {
        const int s = idx >> 7, q = idx & 127;
        xqT[q][s] = xp[idx];
    }
    __syncthreads();
    const float bcv = g_bc[k];
    u64 acc[5];
#pragma unroll
    for (int p = 0; p < 5; ++p) acc[p] = dup2(bcv);
#pragma unroll 4
    for (int i = 0; i < Q; ++i) {
        const u64 wd = dup2(g_Wc[i * H + k]);
#pragma unroll
        for (int p = 0; p < 5; ++p)
            fma2(acc[p], *(const u64*)&xqT[i][2 * p], wd);
    }
    float* o = g_qp + (long long)bt * S * H + k;
#pragma unroll
    for (int p = 0; p < 5; ++p) {
        float v0, v1; un2(acc[p], v0, v1);
        o[(2 * p) * H] = v0; o[(2 * p + 1) * H] = v1;
    }
}

// ---------------- recurrent kernel: 512 threads, 4 warp groups ----------------
__global__ void __launch_bounds__(512, 1) rec_kernel(
    const float* __restrict__ Wattn, const float* __restrict__ battn,
    const int* __restrict__ keys_length, float* __restrict__ out)
{
    extern __shared__ float sm[];
    const int tid = threadIdx.x;
    const int k = tid & 127, wg = tid >> 7;    // wg0,1=attn  wg2,3=gate/cell
    const int lane = tid & 31, warp = tid >> 5;
    const int b = g_perm[blockIdx.x];
    const int kl = keys_length[b];

    {
        const float4* src = (const float4*)(Wattn + HH);
        float4* dst = (float4*)(sm + SM_W1);
        for (int i = tid; i < 3 * HH / 4; i += 512) dst[i] = src[i];
    }
    for (int i = tid; i < 2 * H * 12; i += 512) sm[SM_HT + i] = 0.f;
    __syncthreads();

    float* hT   = sm + SM_HT;
    float* bufT = sm + SM_BUF;

    const float b1v = battn[1 * H + k];
    const float b2v = battn[2 * H + k];
    const float b3v = battn[3 * H + k];

    float c[6];   // wg2: s0..3 (uses [0..3]); wg3: s4..9 (uses [0..5])
#pragma unroll
    for (int s = 0; s < 6; ++s) c[s] = 0.f;

    int t = 0;
    for (; t < kl; ++t) {
        // ===================== parallel section =====================
        if (wg < 2) {
            // ---------- attention (wg0 + wg1, 256 threads) ----------
            if (t > 0) {
                // scores + exp (flat octet indexing over 32 groups)
                const int group = tid >> 3, gl = tid & 7;
                const int nd = S * t;
                const int iters = (nd + 31) >> 5;
                const float tinv = __fdividef(1.f, (float)t);
                const float* qbase = sm + SM_QPS + (t & 1) * (S * H);
                for (int i = 0; i < iters; ++i) {
                    const int idx = group + 32 * i;
                    const bool valid = idx < nd;
                    int s = 0, tp = 0;
                    float acc = 0.f;
                    if (valid) {
                        s = (int)(((float)idx + 0.5f) * tinv);
                        tp = idx - s * t;
                        const float4* pkr = (const float4*)(g_pk + ((long long)((b * T + tp) * S + s)) * H) + gl * 4;
                        const float4* qr  = (const float4*)(qbase + s * H) + gl * 4;
#pragma unroll
                        for (int j = 0; j < 4; ++j) {
                            const float4 q = qr[j], p = pkr[j];
                            acc += q.x * p.x + q.y * p.y + q.z * p.z + q.w * p.w;
                        }
                    }
                    acc += __shfl_xor_sync(0xffffffffu, acc, 1);
                    acc += __shfl_xor_sync(0xffffffffu, acc, 2);
                    acc += __shfl_xor_sync(0xffffffffu, acc, 4);
                    if (valid && gl == 0) sm[SM_SSM + tp * 12 + s] = __expf(acc);
                }
                asm volatile("bar.sync 1, 256;" ::: "memory");

                // row sums -> inverse
                for (int s = warp; s < S; s += 8) {
                    float sum = 0.f;
                    for (int tp = lane; tp < t; tp += 32) sum += sm[SM_SSM + tp * 12 + s];
#pragma unroll
                    for (int o = 16; o > 0; o >>= 1) sum += __shfl_xor_sync(0xffffffffu, sum, o);
                    if (lane == 0) sm[SM_INV + s] = __fdividef(1.f, sum);
                }
                asm volatile("bar.sync 1, 256;" ::: "memory");

                // ctx: wg0 s0-4, wg1 s5-9
                {
                    const int sbase = wg * 5;
                    float cx[5] = {0.f, 0.f, 0.f, 0.f, 0.f};
                    const float* pvb = g_pv + ((long long)b * T * S) * H + k + sbase * H;
#pragma unroll 8
                    for (int tp = 0; tp < t; ++tp) {
                        const float* pr = sm + SM_SSM + tp * 12 + sbase;
                        const float* pvr = pvb + (long long)tp * S * H;
#pragma unroll
                        for (int s = 0; s < 5; ++s) cx[s] += pr[s] * pvr[s * H];
                    }
#pragma unroll
                    for (int s = 0; s < 5; ++s)
                        bufT[k * 12 + sbase + s] = cx[s] * sm[SM_INV + sbase + s];
                }
                asm volatile("bar.sync 1, 256;" ::: "memory");

                if (wg == 0) {
                    // at-GEMM: at = ctx @ W3 + b3 -> ATS
                    u64 At[5];
#pragma unroll
                    for (int p = 0; p < 5; ++p) At[p] = dup2(b3v);
#pragma unroll 8
                    for (int h = 0; h < H; ++h) {
                        const u64 w3 = dup2(sm[SM_W3 + h * H + k]);
                        const float* br = bufT + h * 12;
                        const float4 ba4 = *(const float4*)(br);
                        const float4 bb4 = *(const float4*)(br + 4);
                        const float2 bc2 = *(const float2*)(br + 8);
                        fma2(At[0], pk2(ba4.x, ba4.y), w3);
                        fma2(At[1], pk2(ba4.z, ba4.w), w3);
                        fma2(At[2], pk2(bb4.x, bb4.y), w3);
                        fma2(At[3], pk2(bb4.z, bb4.w), w3);
                        fma2(At[4], pk2(bc2.x, bc2.y), w3);
                    }
#pragma unroll
                    for (int p = 0; p < 5; ++p) {
                        float v0, v1; un2(At[p], v0, v1);
                        sm[SM_ATS + (2 * p) * H + k] = v0;
                        sm[SM_ATS + (2 * p + 1) * H + k] = v1;
                    }
                } else {
                    // wg1: prefetch qp(t+1)
                    const int tn = t + 1;
                    if (tn < kl) {
                        const float* qpp = g_qp + ((long long)(b * T + tn) * S) * H;
                        float* dst = sm + SM_QPS + (tn & 1) * (S * H);
#pragma unroll
                        for (int s = 0; s < S; ++s) dst[s * H + k] = qpp[s * H + k];
                    }
                }
            } else {
                // t == 0: just prefetch qp(1) with wg1
                if (wg == 1 && 1 < kl) {
                    const float* qpp = g_qp + ((long long)(b * T + 1) * S) * H;
                    float* dst = sm + SM_QPS + (1 & 1) * (S * H);
#pragma unroll
                    for (int s = 0; s < S; ++s) dst[s * H + k] = qpp[s * H + k];
                }
            }
            __syncthreads();         // ATS / gates ready

            // cell done by wg2/wg3; wg0/wg1 wait
            __syncthreads();         // hT(t) ready

            // ---- G: pk (wg0) / pv (wg1) ----
            {
                const float* W = (wg == 0) ? (sm + SM_W1) : (sm + SM_W2);
                const float bv = (wg == 0) ? b1v : b2v;
                u64 P[5];
#pragma unroll
                for (int p = 0; p < 5; ++p) P[p] = dup2(bv);
#pragma unroll 8
                for (int h = 0; h < H; ++h) {
                    const u64 w = dup2(W[h * H + k]);
                    const float* hr = hT + h * 12;
                    const float4 ha = *(const float4*)(hr);
                    const float4 hb = *(const float4*)(hr + 4);
                    const float2 hc = *(const float2*)(hr + 8);
                    fma2(P[0], pk2(ha.x, ha.y), w);
                    fma2(P[1], pk2(ha.z, ha.w), w);
                    fma2(P[2], pk2(hb.x, hb.y), w);
                    fma2(P[3], pk2(hb.z, hb.w), w);
                    fma2(P[4], pk2(hc.x, hc.y), w);
                }
                float* gp = ((wg == 0) ? g_pk : g_pv) + ((long long)((b * T + t) * S)) * H + k;
#pragma unroll
                for (int p = 0; p < 5; ++p) {
                    float v0, v1; un2(P[p], v0, v1);
                    gp[(2 * p) * H] = v0; gp[(2 * p + 1) * H] = v1;
                }
            }
        } else {
            // ---------- gate + cell (wg2: s-pairs 0-1, wg3: s-pairs 2-4) ----------
            float a0, a1, a2, a3, td1, td2;
            {
                const float* Ab = g_A + (((long long)(b * T + t)) * H + k) * 6;
                const float2 x01 = *(const float2*)(Ab);
                const float2 x23 = *(const float2*)(Ab + 2);
                const float2 x45 = *(const float2*)(Ab + 4);
                a0 = x01.x; a1 = x01.y; a2 = x23.x; a3 = x23.y;
                td1 = x45.x; td2 = x45.y;
            }
            const int np = (wg == 2) ? 2 : 3;       // pairs this wg owns
            const int pbase = (wg == 2) ? 0 : 2;    // first pair index
            u64 A0[3], A1[3], A2[3], A3[3];
#pragma unroll
            for (int p = 0; p < 3; ++p) { A0[p] = 0ull; A1[p] = 0ull; A2[p] = 0ull; A3[p] = 0ull; }
            const float2* W01 = g_Wh01 + k;
            const float2* W23 = g_Wh23 + k;
#pragma unroll 8
            for (int h = 0; h < H; ++h) {
                const float2 w01 = W01[h * H];
                const float2 w23 = W23[h * H];
                const u64 w0 = dup2(w01.x), w1 = dup2(w01.y);
                const u64 w2 = dup2(w23.x), w3 = dup2(w23.y);
                const float* hr = hT + h * 12 + 2 * pbase;
                if (wg == 2) {
                    const float4 ha = *(const float4*)(hr);
                    u64 hp0 = pk2(ha.x, ha.y), hp1 = pk2(ha.z, ha.w);
                    fma2(A0[0], hp0, w0); fma2(A1[0], hp0, w1);
                    fma2(A2[0], hp0, w2); fma2(A3[0], hp0, w3);
                    fma2(A0[1], hp1, w0); fma2(A1[1], hp1, w1);
                    fma2(A2[1], hp1, w2); fma2(A3[1], hp1, w3);
                } else {
                    const float4 ha = *(const float4*)(hr);
                    const float2 hb = *(const float2*)(hr + 4);
                    u64 hp0 = pk2(ha.x, ha.y), hp1 = pk2(ha.z, ha.w), hp2 = pk2(hb.x, hb.y);
                    fma2(A0[0], hp0, w0); fma2(A1[0], hp0, w1);
                    fma2(A2[0], hp0, w2); fma2(A3[0], hp0, w3);
                    fma2(A0[1], hp1, w0); fma2(A1[1], hp1, w1);
                    fma2(A2[1], hp1, w2); fma2(A3[1], hp1, w3);
                    fma2(A0[2], hp2, w0); fma2(A1[2], hp2, w1);
                    fma2(A2[2], hp2, w2); fma2(A3[2], hp2, w3);
                }
            }
            __syncthreads();         // ATS ready (from wg0)

            // ---- cell for this wg's s-range ----
            {
                float G0[6], G1[6], G2[6], G3[6];
#pragma unroll
                for (int p = 0; p < 3; ++p) {
                    if (p < np) {
                        un2(A0[p], G0[2 * p], G0[2 * p + 1]);
                        un2(A1[p], G1[2 * p], G1[2 * p + 1]);
                        un2(A2[p], G2[2 * p], G2[2 * p + 1]);
                        un2(A3[p], G3[2 * p], G3[2 * p + 1]);
                    }
                }
                const int ns = 2 * np;
                const int sbase = 2 * pbase;
#pragma unroll
                for (int s = 0; s < 6; ++s) {
                    if (s < ns) {
                        const int sg = sbase + s;
                        const float atv = (t > 0) ? sm[SM_ATS + sg * H + k] : 1.f;
                        const float it = sigf(a0 + G0[s]);
                        const float ft = sigf(a1 + G1[s]);
                        const float ct = tanhfast(a2 + G2[s]);
                        const float ot = sigf(a3 + G3[s]);
                        const float itp = it * atv, ftp = ft * atv;
                        const float fc = ftp * c[s];
                        const float ic = itp * ct;
                        const float chat = fc + ic * td1;
                        c[s] = fc + ic * td2;
                        hT[k * 12 + sg] = ot * tanhfast(chat);
                    }
                }
            }
            __syncthreads();         // hT(t) ready

            // ---- G: wg3 writes hidden_seq output; wg2 idle ----
            if (wg == 3) {
                float* outp = out + ((long long)((b * T + t) * S)) * H + k;
#pragma unroll
                for (int s = 0; s < S; ++s) outp[s * H] = hT[k * 12 + s];
            }
        }
        __syncthreads();            // pk/pv(t) visible for scores(t+1)
    }

    // masked steps: zeros (wg0 s0-4, wg1 s5-9)
    if (wg < 2) {
        for (int tz = t; tz < T; ++tz) {
            float* outp = out + ((long long)((b * T + tz) * S)) * H + k;
#pragma unroll
            for (int j = 0; j < 5; ++j) outp[(wg * 5 + j) * H] = 0.f;
        }
    }

    // final h, c (wg2: s0-3, wg3: s4-9)
    if (wg >= 2) {
        const int sbase = (wg == 2) ? 0 : 4;
        const int ns = (wg == 2) ? 4 : 6;
        float* oh = out + HSEQ_ELEMS + ((long long)b * S) * H + k;
        float* oc = oh + HC_ELEMS;
#pragma unroll
        for (int s = 0; s < 6; ++s) {
            if (s < ns) {
                oh[(sbase + s) * H] = hT[k * 12 + sbase + s];
                oc[(sbase + s) * H] = c[s];
            }
        }
    }
}

// ---------------- bce: loss from hseq (parallel post-pass) ----------------
__global__ void __launch_bounds__(128) bce_kernel(
    const float* __restrict__ out, const float* __restrict__ austgn_y,
    const int* __restrict__ keys_length)
{
    const int bt = blockIdx.x;
    const int b = bt >> 6, t = bt & 63;
    const int k = threadIdx.x;
    __shared__ float red[4];
    if (t >= keys_length[b]) {
        if (k == 0) g_lpart[bt] = 0.f;
        return;
    }
    const float y = austgn_y[bt];
    const float* hp = out + ((long long)bt * S) * H + k;
    float bsum = 0.f;
#pragma unroll
    for (int s = 0; s < S; ++s) {
        const float hn = hp[s * H];
        const float p = fminf(fmaxf(hn, 1e-7f), 1.f - 1e-7f);
        bsum += -(y * __logf(p) + (1.f - y) * __logf(1.f - p));
    }
#pragma unroll
    for (int o = 16; o > 0; o >>= 1) bsum += __shfl_xor_sync(0xffffffffu, bsum, o);
    if ((k & 31) == 0) red[k >> 5] = bsum;
    __syncthreads();
    if (k == 0)
        g_lpart[bt] = (red[0] + red[1] + red[2] + red[3]) * g_nvinv[t] * (1.f / (float)(S * H));
}

// ---------------- final deterministic loss reduction ----------------
__global__ void __launch_bounds__(256) loss_kernel(float* __restrict__ out)
{
    __shared__ float smr[256];
    const int i = threadIdx.x;
    float sum = 0.f;
    for (int j = 0; j < 64; ++j) sum += g_lpart[i * 64 + j];
    smr[i] = sum;
    __syncthreads();
    for (int off = 128; off > 0; off >>= 1) {
        if (i < off) smr[i] += smr[i + off];
        __syncthreads();
    }
    if (i == 0) out[HSEQ_ELEMS + 2 * HC_ELEMS] = smr[0];
}

// ---------------- launch ----------------
extern "C" void kernel_launch(void* const* d_in, const int* in_sizes, int n_in,
                              void* d_out, int out_size)
{
    (void)in_sizes; (void)n_in; (void)out_size;
    const float* inputs      = (const float*)d_in[0];
    const float* x_q         = (const float*)d_in[1];
    const float* austgn_y    = (const float*)d_in[2];
    const int*   keys_length = (const int*)  d_in[3];
    const float* Wx          = (const float*)d_in[4];
    const float* Wh          = (const float*)d_in[5];
    const float* Wts         = (const float*)d_in[6];
    const float* bg          = (const float*)d_in[7];
    const float* Wa          = (const float*)d_in[8];
    const float* ba          = (const float*)d_in[9];
    const float* Wattn       = (const float*)d_in[10];
    const float* battn       = (const float*)d_in[11];
    float* out = (float*)d_out;

    static int smem_set = 0;
    if (!smem_set) {
        cudaFuncSetAttribute(rec_kernel, cudaFuncAttributeMaxDynamicSharedMemorySize,
                             SM_TOTAL * (int)sizeof(float));
        smem_set = 1;
    }

    fold_kernel<<<256, 128>>>(Wa, ba, Wattn, battn, Wh, keys_length);
    pre_kernel<<<B, 128>>>(inputs, Wx, Wts, bg, keys_length);
    qp_kernel<<<B * T, 128>>>(x_q, keys_length);
    rec_kernel<<<B, 512, SM_TOTAL * (int)sizeof(float)>>>(
        Wattn, battn, keys_length, out);
    bce_kernel<<<B * T, 128>>>(out, austgn_y, keys_length);
    loss_kernel<<<1, 256>>>(out);
}

// round 15
// speedup vs baseline: 1.5873x; 1.5873x over previous
#include <cuda_runtime.h>
#include <math.h>

namespace {
constexpr int B = 256, T = 64, S = 10, H = 128, IPT = 128, Q = 128;
constexpr int ROWLEN = 2 + IPT;
constexpr int HH = H * H;
constexpr long long HSEQ_ELEMS = (long long)B * T * S * H;
constexpr long long HC_ELEMS   = (long long)B * S * H;
// dynamic smem layout (float offsets)
constexpr int SM_W1  = 0;                   // [128][128] Wattn1
constexpr int SM_WF  = SM_W1 + HH;          // [128][128] Wf = W2@W3
constexpr int SM_HT  = SM_WF + HH;          // [128][12]
constexpr int SM_QPS = SM_HT + H * 12;      // [2][10][128] double-buffered
constexpr int SM_SSM = SM_QPS + 2 * S * H;  // ssmT [64][12]
constexpr int SM_ATS = SM_SSM + T * 12;     // [10][128]
constexpr int SM_INV = SM_ATS + S * H;      // [16]
constexpr int SM_TOTAL = SM_INV + 16;       // 39120 floats = 156480 B
}

// ---------------- scratch ----------------
__device__ float g_qp[B * T * S * H];
__device__ float g_A [B * T * H * 6];       // [B,T,H,6]: a0,a1,a2,a3,td1,td2
__device__ float g_pk[B * T * S * H];
__device__ float g_pw[B * T * S * H];       // pw = h_w @ (W2@W3)
__device__ float g_Wc[H * H];
__device__ float g_bc[H];
__device__ float g_Wf[H * H];               // W2 @ W3
__device__ float g_bf[H];                   // b2 @ W3 + b3
__device__ float2 g_Wh01[H * H];
__device__ float2 g_Wh23[H * H];
__device__ float g_nvinv[T];
__device__ float g_lpart[B * T];
__device__ int   g_perm[B];

// ---------------- f32x2 helpers ----------------
using u64 = unsigned long long;
__device__ __forceinline__ u64 pk2(float lo, float hi) {
    u64 r; asm("mov.b64 %0,{%1,%2};" : "=l"(r) : "f"(lo), "f"(hi)); return r;
}
__device__ __forceinline__ u64 dup2(float x) { return pk2(x, x); }
__device__ __forceinline__ void un2(u64 v, float& a, float& b) {
    asm("mov.b64 {%0,%1},%2;" : "=f"(a), "=f"(b) : "l"(v));
}
__device__ __forceinline__ void fma2(u64& d, u64 a, u64 b) {
    asm("fma.rn.f32x2 %0,%1,%2,%0;" : "+l"(d) : "l"(a), "l"(b));
}

__device__ __forceinline__ float sigf(float x) {
    return __fdividef(1.f, 1.f + __expf(-x));
}
__device__ __forceinline__ float tanhfast(float x) {
    return __fdividef(2.f, 1.f + __expf(-2.f * x)) - 1.f;
}

// ---------------- fold: q-weights + Wf fold + Wh interleave + perm/nvinv ----------------
__global__ void __launch_bounds__(128) fold_kernel(
    const float* __restrict__ Wa, const float* __restrict__ ba,
    const float* __restrict__ Wattn, const float* __restrict__ battn,
    const float* __restrict__ Wh, const int* __restrict__ keys_length)
{
    const int bx = blockIdx.x, tid = threadIdx.x;
    if (bx < 128) {
        const int q = bx, h = tid;
        const float scale = 0.08838834764831845f;
        // g_Wc = (Wa @ Wattn0) * scale
        float acc = 0.f;
        for (int j = 0; j < H; ++j) acc += Wa[q * H + j] * Wattn[j * H + h];
        g_Wc[q * H + h] = acc * scale;
        // g_Wf = W2 @ W3
        const float* W2 = Wattn + 2 * HH;
        const float* W3 = Wattn + 3 * HH;
        float accf = 0.f;
        for (int j = 0; j < H; ++j) accf += W2[q * H + j] * W3[j * H + h];
        g_Wf[q * H + h] = accf;
        if (q == 0) {
            float bacc = battn[h];
            for (int j = 0; j < H; ++j) bacc += ba[j] * Wattn[j * H + h];
            g_bc[h] = bacc * scale;
            // g_bf = b2 @ W3 + b3
            float bfacc = battn[3 * H + h];
            for (int j = 0; j < H; ++j) bfacc += battn[2 * H + j] * W3[j * H + h];
            g_bf[h] = bfacc;
        }
        return;
    }
    const int e = (bx - 128) * 128 + tid;
    g_Wh01[e] = make_float2(Wh[e], Wh[HH + e]);
    g_Wh23[e] = make_float2(Wh[2 * HH + e], Wh[3 * HH + e]);

    if (bx == 128) {
#pragma unroll
        for (int half = 0; half < 2; ++half) {
            const int b = tid + half * 128;
            const int kb = keys_length[b];
            int rank = 0;
            for (int j = 0; j < B; ++j) {
                const int kj = keys_length[j];
                rank += (kj > kb) || (kj == kb && j < b);
            }
            g_perm[rank] = b;
        }
        if (tid < T) {
            int cnt = 0;
            for (int j = 0; j < B; ++j) cnt += (tid < keys_length[j]) ? 1 : 0;
            g_nvinv[tid] = cnt ? 1.f / (float)cnt : 0.f;
        }
    }
}

// ---------------- precompute A[B,T,H,6] (only t < kl) ----------------
__global__ void __launch_bounds__(128) pre_kernel(
    const float* __restrict__ inputs, const float* __restrict__ Wx,
    const float* __restrict__ Wts, const float* __restrict__ bg,
    const int* __restrict__ keys_length)
{
    const int b = blockIdx.x, k = threadIdx.x;
    const int kl = keys_length[b];
    if (kl == 0) return;
    __shared__ float xsT[IPT][66];
    __shared__ float Tts[T], Dts[T];
    const int tmax = kl;
    for (int idx = k; idx < tmax * IPT; idx += 128) {
        const int t = idx >> 7, i = idx & 127;
        xsT[i][t] = inputs[(long long)(b * T + t) * ROWLEN + 2 + i];
    }
    if (k < tmax) {
        Tts[k] = inputs[(long long)(b * T + k) * ROWLEN + 0];
        Dts[k] = inputs[(long long)(b * T + k) * ROWLEN + 1];
    }
    __syncthreads();

    const float wt0 = Wts[0 * H + k], wt1 = Wts[1 * H + k];
    const float wt2 = Wts[2 * H + k], wt3 = Wts[3 * H + k];
    const float wt4 = Wts[4 * H + k], wt5 = Wts[5 * H + k];
    float bgv[8];
#pragma unroll
    for (int g = 0; g < 8; ++g) bgv[g] = bg[g * H + k];

    for (int t0 = 0; t0 < tmax; t0 += 16) {
        const int nt = min(16, tmax - t0);
        float T1v[16], T2v[16];
#pragma unroll
        for (int g = 0; g < 8; ++g) {
            u64 acc[8];
#pragma unroll
            for (int j = 0; j < 8; ++j) acc[j] = 0ull;
            const float* Wg = Wx + (long long)g * IPT * H + k;
#pragma unroll 4
            for (int i = 0; i < IPT; ++i) {
                const u64 wd = dup2(Wg[(long long)i * H]);
#pragma unroll
                for (int j = 0; j < 8; ++j)
                    fma2(acc[j], *(const u64*)&xsT[i][t0 + 2 * j], wd);
            }
#pragma unroll
            for (int j = 0; j < 8; ++j) {
                float v0, v1; un2(acc[j], v0, v1);
#pragma unroll
                for (int half = 0; half < 2; ++half) {
                    const int tt = 2 * j + half;
                    if (tt >= nt) continue;
                    const int t = t0 + tt;
                    const float v = half ? v1 : v0;
                    float* At = g_A + (((long long)(b * T + t)) * H + k) * 6;
                    if (g == 0)      At[0] = v + bgv[0];
                    else if (g == 1) At[1] = v + bgv[1];
                    else if (g == 2) At[2] = v + bgv[2];
                    else if (g == 3) At[3] = v + Tts[t] * wt4 + Dts[t] * wt5 + bgv[3];
                    else if (g == 4) T1v[tt] = sigf(v + sigf(Tts[t] * wt0) + bgv[4]);
                    else if (g == 5) T2v[tt] = sigf(v + sigf(Tts[t] * wt1) + bgv[5]);
                    else if (g == 6) At[4] = T1v[tt] * sigf(v + sigf(Dts[t] * wt2) + bgv[6]);
                    else             At[5] = T2v[tt] * sigf(v + sigf(Dts[t] * wt3) + bgv[7]);
                }
            }
        }
    }
}

// ---------------- qp = x_q @ Wc + bc (only 1 <= t < kl) ----------------
__global__ void __launch_bounds__(128) qp_kernel(
    const float* __restrict__ x_q, const int* __restrict__ keys_length)
{
    const int bt = blockIdx.x, k = threadIdx.x;
    const int b = bt >> 6, t = bt & 63;
    if (t == 0 || t >= keys_length[b]) return;
    __shared__ float xqT[Q][12];
    const float* xp = x_q + (long long)bt * S * Q;
    for (int idx = k; idx < S * Q; idx += 128) {
        const int s = idx >> 7, q = idx & 127;
        xqT[q][s] = xp[idx];
    }
    __syncthreads();
    const float bcv = g_bc[k];
    u64 acc[5];
#pragma unroll
    for (int p = 0; p < 5; ++p) acc[p] = dup2(bcv);
#pragma unroll 4
    for (int i = 0; i < Q; ++i) {
        const u64 wd = dup2(g_Wc[i * H + k]);
#pragma unroll
        for (int p = 0; p < 5; ++p)
            fma2(acc[p], *(const u64*)&xqT[i][2 * p], wd);
    }
    float* o = g_qp + (long long)bt * S * H + k;
#pragma unroll
    for (int p = 0; p < 5; ++p) {
        float v0, v1; un2(acc[p], v0, v1);
        o[(2 * p) * H] = v0; o[(2 * p + 1) * H] = v1;
    }
}

// ---------------- recurrent kernel: warp-group specialized, at-GEMM folded ----------------
__global__ void __launch_bounds__(256, 1) rec_kernel(
    const float* __restrict__ Wattn, const float* __restrict__ battn,
    const int* __restrict__ keys_length, float* __restrict__ out)
{
    extern __shared__ float sm[];
    const int tid = threadIdx.x;
    const int k = tid & 127, wg = tid >> 7;    // wg0=attn+pk, wg1=gate+cell+pw
    const int lane = tid & 31, warp = tid >> 5;
    const int b = g_perm[blockIdx.x];
    const int kl = keys_length[b];

    // preload W1 (from Wattn) and Wf (from g_Wf) into smem
    {
        const float4* src1 = (const float4*)(Wattn + HH);
        const float4* srcf = (const float4*)(g_Wf);
        float4* dst1 = (float4*)(sm + SM_W1);
        float4* dstf = (float4*)(sm + SM_WF);
        for (int i = tid; i < HH / 4; i += 256) { dst1[i] = src1[i]; dstf[i] = srcf[i]; }
    }
    for (int i = tid; i < H * 12; i += 256) sm[SM_HT + i] = 0.f;
    __syncthreads();

    float* hT = sm + SM_HT;

    const float b1v = battn[1 * H + k];
    const float bfv = g_bf[k];

    float c[S];
#pragma unroll
    for (int s = 0; s < S; ++s) c[s] = 0.f;

    int t = 0;
    for (; t < kl; ++t) {
        // ===================== parallel section =====================
        u64 A0[5], A1[5], A2[5], A3[5];      // gate accumulators (wg1)
        float a0 = 0.f, a1 = 0.f, a2 = 0.f, a3 = 0.f, td1 = 0.f, td2 = 0.f;

        if (wg == 0) {
            // ---------- attention warps ----------
            if (t > 0) {
                // B': scores + exp (flat 16-octet indexing)
                const int group = tid >> 3, gl = tid & 7;
                const int nd = S * t;
                const int iters = (nd + 15) >> 4;
                const float tinv = __fdividef(1.f, (float)t);
                const float* qbase = sm + SM_QPS + (t & 1) * (S * H);
                for (int i = 0; i < iters; ++i) {
                    const int idx = group + 16 * i;
                    const bool valid = idx < nd;
                    int s = 0, tp = 0;
                    float acc = 0.f;
                    if (valid) {
                        s = (int)(((float)idx + 0.5f) * tinv);
                        tp = idx - s * t;
                        const float4* pkr = (const float4*)(g_pk + ((long long)((b * T + tp) * S + s)) * H) + gl * 4;
                        const float4* qr  = (const float4*)(qbase + s * H) + gl * 4;
#pragma unroll
                        for (int j = 0; j < 4; ++j) {
                            const float4 q = qr[j], p = pkr[j];
                            acc += q.x * p.x + q.y * p.y + q.z * p.z + q.w * p.w;
                        }
                    }
                    acc += __shfl_xor_sync(0xffffffffu, acc, 1);
                    acc += __shfl_xor_sync(0xffffffffu, acc, 2);
                    acc += __shfl_xor_sync(0xffffffffu, acc, 4);
                    if (valid && gl == 0) sm[SM_SSM + tp * 12 + s] = __expf(acc);
                }
                asm volatile("bar.sync 1, 128;" ::: "memory");

                // C': row sums -> inverse
                for (int s = warp; s < S; s += 4) {
                    float sum = 0.f;
                    for (int tp = lane; tp < t; tp += 32) sum += sm[SM_SSM + tp * 12 + s];
#pragma unroll
                    for (int o = 16; o > 0; o >>= 1) sum += __shfl_xor_sync(0xffffffffu, sum, o);
                    if (lane == 0) sm[SM_INV + s] = __fdividef(1.f, sum);
                }
                asm volatile("bar.sync 1, 128;" ::: "memory");

                // D': at = (sum_tp p * pw) * inv + bf  -> ATS directly
                {
                    float cx[S];
#pragma unroll
                    for (int s = 0; s < S; ++s) cx[s] = 0.f;
                    const float* pwb = g_pw + ((long long)b * T * S) * H + k;
#pragma unroll 4
                    for (int tp = 0; tp < t; ++tp) {
                        const float4 pa = *(const float4*)(sm + SM_SSM + tp * 12);
                        const float4 pbv = *(const float4*)(sm + SM_SSM + tp * 12 + 4);
                        const float2 pc = *(const float2*)(sm + SM_SSM + tp * 12 + 8);
                        const float* pwr = pwb + (long long)tp * S * H;
                        cx[0] += pa.x * pwr[0];
                        cx[1] += pa.y * pwr[H];
                        cx[2] += pa.z * pwr[2 * H];
                        cx[3] += pa.w * pwr[3 * H];
                        cx[4] += pbv.x * pwr[4 * H];
                        cx[5] += pbv.y * pwr[5 * H];
                        cx[6] += pbv.z * pwr[6 * H];
                        cx[7] += pbv.w * pwr[7 * H];
                        cx[8] += pc.x * pwr[8 * H];
                        cx[9] += pc.y * pwr[9 * H];
                    }
#pragma unroll
                    for (int s = 0; s < S; ++s)
                        sm[SM_ATS + s * H + k] = cx[s] * sm[SM_INV + s] + bfv;
                }
            }
            // prefetch qp(t+1) into the other buffer
            {
                const int tn = t + 1;
                if (tn < kl) {
                    const float* qpp = g_qp + ((long long)(b * T + tn) * S) * H;
                    float* dst = sm + SM_QPS + (tn & 1) * (S * H);
#pragma unroll
                    for (int s = 0; s < S; ++s) dst[s * H + k] = qpp[s * H + k];
                }
            }
        } else {
            // ---------- gate warps: A prefetch + 4-gate GEMM ----------
            {
                const float* Ab = g_A + (((long long)(b * T + t)) * H + k) * 6;
                const float2 x01 = *(const float2*)(Ab);
                const float2 x23 = *(const float2*)(Ab + 2);
                const float2 x45 = *(const float2*)(Ab + 4);
                a0 = x01.x; a1 = x01.y; a2 = x23.x; a3 = x23.y;
                td1 = x45.x; td2 = x45.y;
            }
#pragma unroll
            for (int p = 0; p < 5; ++p) { A0[p] = 0ull; A1[p] = 0ull; A2[p] = 0ull; A3[p] = 0ull; }
            const float2* W01 = g_Wh01 + k;
            const float2* W23 = g_Wh23 + k;
#pragma unroll 8
            for (int h = 0; h < H; ++h) {
                const float2 w01 = W01[h * H];
                const float2 w23 = W23[h * H];
                const u64 w0 = dup2(w01.x), w1 = dup2(w01.y);
                const u64 w2 = dup2(w23.x), w3 = dup2(w23.y);
                const float* hr = hT + h * 12;
                const float4 ha = *(const float4*)(hr);
                const float4 hb = *(const float4*)(hr + 4);
                const float2 hc = *(const float2*)(hr + 8);
                u64 hp[5];
                hp[0] = pk2(ha.x, ha.y); hp[1] = pk2(ha.z, ha.w);
                hp[2] = pk2(hb.x, hb.y); hp[3] = pk2(hb.z, hb.w);
                hp[4] = pk2(hc.x, hc.y);
#pragma unroll
                for (int p = 0; p < 5; ++p) {
                    fma2(A0[p], hp[p], w0); fma2(A1[p], hp[p], w1);
                    fma2(A2[p], hp[p], w2); fma2(A3[p], hp[p], w3);
                }
            }
        }
        __syncthreads();            // gates in regs, ATS ready

        // ===================== cell (wg1) =====================
        if (wg == 1) {
            float G0[S], G1[S], G2[S], G3[S];
#pragma unroll
            for (int p = 0; p < 5; ++p) {
                un2(A0[p], G0[2 * p], G0[2 * p + 1]);
                un2(A1[p], G1[2 * p], G1[2 * p + 1]);
                un2(A2[p], G2[2 * p], G2[2 * p + 1]);
                un2(A3[p], G3[2 * p], G3[2 * p + 1]);
            }
#pragma unroll
            for (int s = 0; s < S; ++s) {
                const float atv = (t > 0) ? sm[SM_ATS + s * H + k] : 1.f;
                const float it = sigf(a0 + G0[s]);
                const float ft = sigf(a1 + G1[s]);
                const float ct = tanhfast(a2 + G2[s]);
                const float ot = sigf(a3 + G3[s]);
                const float itp = it * atv, ftp = ft * atv;
                const float fc = ftp * c[s];
                const float ic = itp * ct;
                const float chat = fc + ic * td1;
                c[s] = fc + ic * td2;
                hT[k * 12 + s] = ot * tanhfast(chat);
            }
        }
        __syncthreads();            // hT(t) ready

        // ===================== G: pk (wg0) / pw + out (wg1) =====================
        if (wg == 0) {
            u64 P[5];
#pragma unroll
            for (int p = 0; p < 5; ++p) P[p] = dup2(b1v);
#pragma unroll 8
            for (int h = 0; h < H; ++h) {
                const u64 w = dup2(sm[SM_W1 + h * H + k]);
                const float* hr = hT + h * 12;
                const float4 ha = *(const float4*)(hr);
                const float4 hb = *(const float4*)(hr + 4);
                const float2 hc = *(const float2*)(hr + 8);
                fma2(P[0], pk2(ha.x, ha.y), w);
                fma2(P[1], pk2(ha.z, ha.w), w);
                fma2(P[2], pk2(hb.x, hb.y), w);
                fma2(P[3], pk2(hb.z, hb.w), w);
                fma2(P[4], pk2(hc.x, hc.y), w);
            }
            float* pkp = g_pk + ((long long)((b * T + t) * S)) * H + k;
#pragma unroll
            for (int p = 0; p < 5; ++p) {
                float v0, v1; un2(P[p], v0, v1);
                pkp[(2 * p) * H] = v0; pkp[(2 * p + 1) * H] = v1;
            }
        } else {
            // pw = h_w @ Wf  (bias folded into bf)
            u64 P[5];
#pragma unroll
            for (int p = 0; p < 5; ++p) P[p] = 0ull;
#pragma unroll 8
            for (int h = 0; h < H; ++h) {
                const u64 w = dup2(sm[SM_WF + h * H + k]);
                const float* hr = hT + h * 12;
                const float4 ha = *(const float4*)(hr);
                const float4 hb = *(const float4*)(hr + 4);
                const float2 hc = *(const float2*)(hr + 8);
                fma2(P[0], pk2(ha.x, ha.y), w);
                fma2(P[1], pk2(ha.z, ha.w), w);
                fma2(P[2], pk2(hb.x, hb.y), w);
                fma2(P[3], pk2(hb.z, hb.w), w);
                fma2(P[4], pk2(hc.x, hc.y), w);
            }
            float* pwp = g_pw + ((long long)((b * T + t) * S)) * H + k;
#pragma unroll
            for (int p = 0; p < 5; ++p) {
                float v0, v1; un2(P[p], v0, v1);
                pwp[(2 * p) * H] = v0; pwp[(2 * p + 1) * H] = v1;
            }
            float* outp = out + ((long long)((b * T + t) * S)) * H + k;
#pragma unroll
            for (int s = 0; s < S; ++s) outp[s * H] = hT[k * 12 + s];
        }
        __syncthreads();            // pk/pw(t) visible for step t+1
    }

    // masked steps: zeros
    for (; t < T; ++t) {
        float* outp = out + ((long long)((b * T + t) * S)) * H + k;
#pragma unroll
        for (int j = 0; j < 5; ++j) outp[(wg * 5 + j) * H] = 0.f;
    }

    // final h, c (wg1 holds c)
    if (wg == 1) {
        float* oh = out + HSEQ_ELEMS + ((long long)b * S) * H + k;
#pragma unroll
        for (int s = 0; s < S; ++s) oh[s * H] = hT[k * 12 + s];
        float* oc = oh + HC_ELEMS;
#pragma unroll
        for (int s = 0; s < S; ++s) oc[s * H] = c[s];
    }
}

// ---------------- bce: loss from hseq (parallel post-pass) ----------------
__global__ void __launch_bounds__(128) bce_kernel(
    const float* __restrict__ out, const float* __restrict__ austgn_y,
    const int* __restrict__ keys_length)
{
    const int bt = blockIdx.x;
    const int b = bt >> 6, t = bt & 63;
    const int k = threadIdx.x;
    __shared__ float red[4];
    if (t >= keys_length[b]) {
        if (k == 0) g_lpart[bt] = 0.f;
        return;
    }
    const float y = austgn_y[bt];
    const float* hp = out + ((long long)bt * S) * H + k;
    float bsum = 0.f;
#pragma unroll
    for (int s = 0; s < S; ++s) {
        const float hn = hp[s * H];
        const float p = fminf(fmaxf(hn, 1e-7f), 1.f - 1e-7f);
        bsum += -(y * __logf(p) + (1.f - y) * __logf(1.f - p));
    }
#pragma unroll
    for (int o = 16; o > 0; o >>= 1) bsum += __shfl_xor_sync(0xffffffffu, bsum, o);
    if ((k & 31) == 0) red[k >> 5] = bsum;
    __syncthreads();
    if (k == 0)
        g_lpart[bt] = (red[0] + red[1] + red[2] + red[3]) * g_nvinv[t] * (1.f / (float)(S * H));
}

// ---------------- final deterministic loss reduction ----------------
__global__ void __launch_bounds__(256) loss_kernel(float* __restrict__ out)
{
    __shared__ float smr[256];
    const int i = threadIdx.x;
    float sum = 0.f;
    for (int j = 0; j < 64; ++j) sum += g_lpart[i * 64 + j];
    smr[i] = sum;
    __syncthreads();
    for (int off = 128; off > 0; off >>= 1) {
        if (i < off) smr[i] += smr[i + off];
        __syncthreads();
    }
    if (i == 0) out[HSEQ_ELEMS + 2 * HC_ELEMS] = smr[0];
}

// ---------------- launch ----------------
extern "C" void kernel_launch(void* const* d_in, const int* in_sizes, int n_in,
                              void* d_out, int out_size)
{
    (void)in_sizes; (void)n_in; (void)out_size;
    const float* inputs      = (const float*)d_in[0];
    const float* x_q         = (const float*)d_in[1];
    const float* austgn_y    = (const float*)d_in[2];
    const int*   keys_length = (const int*)  d_in[3];
    const float* Wx          = (const float*)d_in[4];
    const float* Wh          = (const float*)d_in[5];
    const float* Wts         = (const float*)d_in[6];
    const float* bg          = (const float*)d_in[7];
    const float* Wa          = (const float*)d_in[8];
    const float* ba          = (const float*)d_in[9];
    const float* Wattn       = (const float*)d_in[10];
    const float* battn       = (const float*)d_in[11];
    float* out = (float*)d_out;

    static int smem_set = 0;
    if (!smem_set) {
        cudaFuncSetAttribute(rec_kernel, cudaFuncAttributeMaxDynamicSharedMemorySize,
                             SM_TOTAL * (int)sizeof(float));
        smem_set = 1;
    }

    fold_kernel<<<256, 128>>>(Wa, ba, Wattn, battn, Wh, keys_length);
    pre_kernel<<<B, 128>>>(inputs, Wx, Wts, bg, keys_length);
    qp_kernel<<<B * T, 128>>>(x_q, keys_length);
    rec_kernel<<<B, 256, SM_TOTAL * (int)sizeof(float)>>>(
        Wattn, battn, keys_length, out);
    bce_kernel<<<B * T, 128>>>(out, austgn_y, keys_length);
    loss_kernel<<<1, 256>>>(out);
}